// round 14
// baseline (speedup 1.0000x reference)
#include <cuda_runtime.h>

// LovaszSoftmaxV1 — histogram/Abel-summation (no sort). R14:
// prep made elementwise (no v[19] -> no register spills): minpos writes
// inv_sum[m] + packed labels; prep processes 22.4M (c,m) elements directly.

#define LSV_CLS  19
#define LSV_HW   (384 * 384)           // 147456
#define LSV_MPIX (8 * LSV_HW)          // 1179648
#define LSV_BINS 2048
#define LSV_KPB  2                     // bins per thread in scan

#define LSV_MPB  1024                  // minpos: pixels per block (256 x 4)
#define LSV_MNB  (LSV_MPIX / LSV_MPB)  // 1152
#define LSV_ENB  (LSV_MPIX / 1024)     // prep: elems-per-class-row blocks

__device__ unsigned int  lsvE_hneg[LSV_CLS * LSV_BINS];
__device__ unsigned int  lsvE_hpos[LSV_CLS * LSV_BINS];
__device__ int           lsvE_minbin[LSV_CLS];
__device__ float         lsvE_inv[LSV_MPIX];     // 1 / sum(exp) per pixel
__device__ unsigned char lsvE_lbl8[LSV_MPIX];
__device__ double        lsvE_cls_loss[LSV_CLS];
__device__ int           lsvE_lbl_is32;

__device__ __forceinline__ int lsvE_bin(float e) {
    int b = (int)(e * (float)LSV_BINS);
    return min(max(b, 0), LSV_BINS - 1);
}

// ---------------------------------------------------------------------------
__global__ void lsvE_zero() {
    int i = blockIdx.x * blockDim.x + threadIdx.x;
    if (i < LSV_CLS * LSV_BINS) { lsvE_hneg[i] = 0u; lsvE_hpos[i] = 0u; }
    if (i < LSV_CLS) lsvE_minbin[i] = 0x7fffffff;
    if (i == 0) lsvE_lbl_is32 = 0;
}

// ---------------------------------------------------------------------------
// Label dtype detector (int32 vs int64): odd int32-words of an int64(<19)
// little-endian buffer are all zero.
// ---------------------------------------------------------------------------
__global__ void __launch_bounds__(256) lsvE_detect(const int* __restrict__ w) {
    int i = blockIdx.x * blockDim.x + threadIdx.x;
    int idx = 2 * i + 1;
    int v = (idx < LSV_MPIX) ? w[idx] : 0;
    for (int off = 16; off > 0; off >>= 1)
        v |= __shfl_down_sync(0xffffffffu, v, off);
    if ((threadIdx.x & 31) == 0 && v != 0) atomicOr(&lsvE_lbl_is32, 1);
}

// ---------------------------------------------------------------------------
// Kernel 1: online softmax pass -> per-class min positive bin + inv_sum[m]
// + packed u8 labels. Low-reg (online accumulation, nothing held per class).
// ---------------------------------------------------------------------------
__global__ void __launch_bounds__(256) lsvE_minpos(
    const float* __restrict__ logits,
    const int* __restrict__ lblw)
{
    __shared__ int smin[LSV_CLS];
    int tid = threadIdx.x;
    if (tid < LSV_CLS) smin[tid] = 0x7fffffff;
    __syncthreads();

    int base_m = blockIdx.x * LSV_MPB + tid;
    int n  = base_m / LSV_HW;          // whole block shares one image
    int hw0 = base_m - n * LSV_HW;
    const float* lg = logits + (size_t)n * (LSV_CLS * LSV_HW) + hw0;
    int is32 = lsvE_lbl_is32;

    int lb[4];
    float s[4]    = {0.f, 0.f, 0.f, 0.f};
    float evlb[4] = {0.f, 0.f, 0.f, 0.f};
#pragma unroll
    for (int i = 0; i < 4; i++) {
        int m = base_m + i * 256;
        lb[i] = is32 ? lblw[m] : lblw[2 * m];
        lsvE_lbl8[m] = (unsigned char)lb[i];
    }
#pragma unroll
    for (int c = 0; c < LSV_CLS; c++) {
        const float* row = lg + (size_t)c * LSV_HW;
#pragma unroll
        for (int i = 0; i < 4; i++) {
            float ev = __expf(__ldcs(row + i * 256));
            s[i] += ev;
            if (c == lb[i]) evlb[i] = ev;
        }
    }
#pragma unroll
    for (int i = 0; i < 4; i++) {
        float inv = 1.0f / s[i];
        lsvE_inv[base_m + i * 256] = inv;
        if ((unsigned)lb[i] < LSV_CLS) {
            float e = 1.0f - evlb[i] * inv;
            atomicMin(&smin[lb[i]], lsvE_bin(e));
        }
    }
    __syncthreads();
    if (tid < LSV_CLS && smin[tid] != 0x7fffffff)
        atomicMin(&lsvE_minbin[tid], smin[tid]);
}

// ---------------------------------------------------------------------------
// Kernel 2: elementwise over (c, m). grid = (1152, 19); thread handles 4
// elements strided by 256 within one class row. e = |onehot - exp(v)*inv[m]|,
// store to errs, filtered atomic (Delta-jaccard == 0 below min positive bin).
// inv[] and lbl8[] working set is 5.9MB -> L2-resident across the 19 re-reads.
// ---------------------------------------------------------------------------
__global__ void __launch_bounds__(256) lsvE_prep(
    const float* __restrict__ logits,
    float* __restrict__ errs)
{
    int c = blockIdx.y;
    int base_m = blockIdx.x * 1024 + threadIdx.x;
    int n  = base_m / LSV_HW;          // whole block shares one image
    int hw0 = base_m - n * LSV_HW;
    const float* row = logits + ((size_t)n * LSV_CLS + c) * LSV_HW + hw0;

    int mb = lsvE_minbin[c];
    if (mb == 0x7fffffff) mb = 0;

    // Front-batched independent loads.
    float v[4], inv[4];
    unsigned char lb[4];
#pragma unroll
    for (int i = 0; i < 4; i++) v[i] = __ldcs(row + i * 256);
#pragma unroll
    for (int i = 0; i < 4; i++) inv[i] = lsvE_inv[base_m + i * 256];
#pragma unroll
    for (int i = 0; i < 4; i++) lb[i]  = lsvE_lbl8[base_m + i * 256];

    float* erow = errs + (size_t)c * LSV_MPIX + base_m;
    unsigned int* hp = lsvE_hpos + c * LSV_BINS;
    unsigned int* hn = lsvE_hneg + c * LSV_BINS;
#pragma unroll
    for (int i = 0; i < 4; i++) {
        float p = __expf(v[i]) * inv[i];
        bool g = (lb[i] == (unsigned char)c);
        float e = g ? (1.0f - p) : p;
        __stcs(erow + i * 256, e);
        int bin = lsvE_bin(e);
        if (bin >= mb) atomicAdd(g ? &hp[bin] : &hn[bin], 1u);
    }
}

// ---------------------------------------------------------------------------
// Scan: per-class Lovasz loss from split histograms (single pass, one fp64
// div per nonempty bin). j(cnt,cp) = 1 - (P-cp)/(P+cnt-cp), j(0,0) := 0.
// ---------------------------------------------------------------------------
__global__ void __launch_bounds__(1024) lsvE_scan() {
    const int c = blockIdx.x;
    const unsigned int* hn = lsvE_hneg + (size_t)c * LSV_BINS;
    const unsigned int* hp = lsvE_hpos + (size_t)c * LSV_BINS;
    int t = threadIdx.x, lane = t & 31, wid = t >> 5;

    unsigned int xn[LSV_KPB], xp[LSV_KPB];
    unsigned long long tot = 0ull;   // count | positives<<32
#pragma unroll
    for (int k = 0; k < LSV_KPB; k++) {
        int b = LSV_BINS - 1 - (t * LSV_KPB + k);
        xn[k] = hn[b]; xp[k] = hp[b];
        tot += (unsigned long long)(xn[k] + xp[k])
             + ((unsigned long long)xp[k] << 32);
    }

    __shared__ unsigned long long wsum[32];
    unsigned long long v = tot;
#pragma unroll
    for (int off = 1; off < 32; off <<= 1) {
        unsigned long long u = __shfl_up_sync(0xffffffffu, v, off);
        if (lane >= off) v += u;
    }
    if (lane == 31) wsum[wid] = v;
    __syncthreads();
    if (wid == 0) {
        unsigned long long w = wsum[lane];
#pragma unroll
        for (int off = 1; off < 32; off <<= 1) {
            unsigned long long u = __shfl_up_sync(0xffffffffu, w, off);
            if (lane >= off) w += u;
        }
        wsum[lane] = w;
    }
    __syncthreads();
    unsigned long long excl = v - tot;
    if (wid > 0) excl += wsum[wid - 1];
    long long P = (long long)(wsum[31] >> 32);

    long long cnt = (long long)(excl & 0xffffffffull);
    long long cp  = (long long)(excl >> 32);
    double jprev = (cnt == 0) ? 0.0
                 : 1.0 - (double)(P - cp) / (double)(P + cnt - cp);
    double loss = 0.0;
#pragma unroll
    for (int k = 0; k < LSV_KPB; k++) {
        int b = LSV_BINS - 1 - (t * LSV_KPB + k);
        long long nb = (long long)xn[k] + xp[k];
        if (nb > 0) {
            cnt += nb; cp += xp[k];
            double j1 = 1.0 - (double)(P - cp) / (double)(P + cnt - cp);
            loss += (((double)b + 0.5) / (double)LSV_BINS) * (j1 - jprev);
            jprev = j1;
        }
    }

    __shared__ double sl[32];
#pragma unroll
    for (int off = 16; off > 0; off >>= 1)
        loss += __shfl_down_sync(0xffffffffu, loss, off);
    if (lane == 0) sl[wid] = loss;
    __syncthreads();
    if (wid == 0) {
        double l = sl[lane];
#pragma unroll
        for (int off = 16; off > 0; off >>= 1)
            l += __shfl_down_sync(0xffffffffu, l, off);
        if (lane == 0) lsvE_cls_loss[c] = l;
    }
}

// ---------------------------------------------------------------------------
__global__ void lsvE_finalize(float* __restrict__ out) {
    double s = 0.0;
#pragma unroll
    for (int c = 0; c < LSV_CLS; c++) s += lsvE_cls_loss[c];
    out[0] = (float)(s / (double)LSV_CLS);
}

// ---------------------------------------------------------------------------
extern "C" void kernel_launch(void* const* d_in, const int* in_sizes, int n_in,
                              void* d_out, int out_size) {
    const float* logits = (const float*)d_in[0];
    const int*   lblw   = (const int*)d_in[1];
    float* out = (float*)d_out;

    const long long full = (long long)LSV_CLS * LSV_MPIX;
    long long off = (long long)out_size - full;
    if (off < 0) off = 0;
    float* errs_ptr = out + off;

    lsvE_zero<<<(LSV_CLS * LSV_BINS + 255) / 256, 256>>>();
    lsvE_detect<<<(LSV_MPIX / 2 + 255) / 256, 256>>>(lblw);
    lsvE_minpos<<<LSV_MNB, 256>>>(logits, lblw);
    {
        dim3 g(LSV_ENB, LSV_CLS);
        lsvE_prep<<<g, 256>>>(logits, errs_ptr);
    }
    lsvE_scan<<<LSV_CLS, 1024>>>();
    if (off > 0) lsvE_finalize<<<1, 1>>>(out);
}

// round 15
// speedup vs baseline: 1.7869x; 1.7869x over previous
#include <cuda_runtime.h>

// LovaszSoftmaxV1 — histogram/Abel-summation (no sort). R15 (base = R13):
// prep: 2 px/thread, float2 logit loads, __launch_bounds__(256,4) => 64-reg
// budget, v[2][19] fully in registers (no spills), 19 batched LDG.64.
// minpos: float4 logit loads (read-only kernel, alignment safe).

#define LSV_CLS  19
#define LSV_HW   (384 * 384)           // 147456
#define LSV_MPIX (8 * LSV_HW)          // 1179648
#define LSV_BINS 2048
#define LSV_KPB  2                     // bins per thread in scan

#define LSV_MPB  1024                  // minpos: pixels per block (256 x 4)
#define LSV_MNB  (LSV_MPIX / LSV_MPB)  // 1152
#define LSV_PNB  (LSV_MPIX / 512)      // prep: 2304 blocks (256 thr x 2 px)

__device__ unsigned int lsvF_hneg[LSV_CLS * LSV_BINS];
__device__ unsigned int lsvF_hpos[LSV_CLS * LSV_BINS];
__device__ int          lsvF_minbin[LSV_CLS];
__device__ double       lsvF_cls_loss[LSV_CLS];
__device__ int          lsvF_lbl_is32;

__device__ __forceinline__ int lsvF_bin(float e) {
    int b = (int)(e * (float)LSV_BINS);
    return min(max(b, 0), LSV_BINS - 1);
}

// ---------------------------------------------------------------------------
__global__ void lsvF_zero() {
    int i = blockIdx.x * blockDim.x + threadIdx.x;
    if (i < LSV_CLS * LSV_BINS) { lsvF_hneg[i] = 0u; lsvF_hpos[i] = 0u; }
    if (i < LSV_CLS) lsvF_minbin[i] = 0x7fffffff;
    if (i == 0) lsvF_lbl_is32 = 0;
}

// ---------------------------------------------------------------------------
// Label dtype detector (int32 vs int64): odd int32-words of an int64(<19)
// little-endian buffer are all zero.
// ---------------------------------------------------------------------------
__global__ void __launch_bounds__(256) lsvF_detect(const int* __restrict__ w) {
    int i = blockIdx.x * blockDim.x + threadIdx.x;
    int idx = 2 * i + 1;
    int v = (idx < LSV_MPIX) ? w[idx] : 0;
    for (int off = 16; off > 0; off >>= 1)
        v |= __shfl_down_sync(0xffffffffu, v, off);
    if ((threadIdx.x & 31) == 0 && v != 0) atomicOr(&lsvF_lbl_is32, 1);
}

// ---------------------------------------------------------------------------
// Kernel 1: min positive bin per class — online softmax, float4 logit loads.
// Thread t handles the 4 consecutive pixels of float4 index (b*256 + t).
// ---------------------------------------------------------------------------
__global__ void __launch_bounds__(256) lsvF_minpos(
    const float* __restrict__ logits,
    const int* __restrict__ lblw)
{
    __shared__ int smin[LSV_CLS];
    int tid = threadIdx.x;
    if (tid < LSV_CLS) smin[tid] = 0x7fffffff;
    __syncthreads();

    int q = blockIdx.x * 256 + tid;    // float4 index
    int base_m = q * 4;
    int n  = base_m / LSV_HW;          // 4 pixels never straddle images
    int hw0 = base_m - n * LSV_HW;
    const float* lg = logits + (size_t)n * (LSV_CLS * LSV_HW) + hw0;
    int is32 = lsvF_lbl_is32;

    int lb[4];
#pragma unroll
    for (int i = 0; i < 4; i++) {
        int m = base_m + i;
        lb[i] = is32 ? lblw[m] : lblw[2 * m];
    }

    float s[4]    = {0.f, 0.f, 0.f, 0.f};
    float evlb[4] = {0.f, 0.f, 0.f, 0.f};
#pragma unroll
    for (int c = 0; c < LSV_CLS; c++) {
        float4 x = __ldcs((const float4*)(lg + (size_t)c * LSV_HW));
        float ev0 = __expf(x.x), ev1 = __expf(x.y);
        float ev2 = __expf(x.z), ev3 = __expf(x.w);
        s[0] += ev0; s[1] += ev1; s[2] += ev2; s[3] += ev3;
        if (c == lb[0]) evlb[0] = ev0;
        if (c == lb[1]) evlb[1] = ev1;
        if (c == lb[2]) evlb[2] = ev2;
        if (c == lb[3]) evlb[3] = ev3;
    }
#pragma unroll
    for (int i = 0; i < 4; i++) {
        if ((unsigned)lb[i] < LSV_CLS) {
            float e = 1.0f - evlb[i] / s[i];
            atomicMin(&smin[lb[i]], lsvF_bin(e));
        }
    }
    __syncthreads();
    if (tid < LSV_CLS && smin[tid] != 0x7fffffff)
        atomicMin(&lsvF_minbin[tid], smin[tid]);
}

// ---------------------------------------------------------------------------
// Kernel 2: single-pass prep, 2 pixels/thread (float2 logit loads, v[2][19]
// in registers under a 64-reg budget). Stream errs out (scalar stores, out+1
// safe) and issue min-positive-bin-filtered atomics.
// ---------------------------------------------------------------------------
__global__ void __launch_bounds__(256, 4) lsvF_prep(
    const float* __restrict__ logits,
    const int* __restrict__ lblw,
    float* __restrict__ errs)
{
    __shared__ int smb[LSV_CLS];
    int tid = threadIdx.x;
    if (tid < LSV_CLS) {
        int mb = lsvF_minbin[tid];
        smb[tid] = (mb == 0x7fffffff) ? 0 : mb;
    }
    __syncthreads();

    int q = blockIdx.x * 256 + tid;    // float2 index
    int base_m = q * 2;
    int n  = base_m / LSV_HW;          // 2 pixels never straddle images
    int hw0 = base_m - n * LSV_HW;
    const float* lg = logits + (size_t)n * (LSV_CLS * LSV_HW) + hw0;
    int is32 = lsvF_lbl_is32;

    int lb0 = is32 ? lblw[base_m]     : lblw[2 * base_m];
    int lb1 = is32 ? lblw[base_m + 1] : lblw[2 * base_m + 2];

    float2 v[LSV_CLS];
#pragma unroll
    for (int c = 0; c < LSV_CLS; c++)
        v[c] = __ldcs((const float2*)(lg + (size_t)c * LSV_HW));

    float s0 = 0.f, s1 = 0.f;
#pragma unroll
    for (int c = 0; c < LSV_CLS; c++) {
        v[c].x = __expf(v[c].x); s0 += v[c].x;
        v[c].y = __expf(v[c].y); s1 += v[c].y;
    }
    float inv0 = 1.0f / s0, inv1 = 1.0f / s1;

#pragma unroll
    for (int c = 0; c < LSV_CLS; c++) {
        float* erow = errs + (size_t)c * LSV_MPIX + base_m;
        int mb = smb[c];

        float p0 = v[c].x * inv0;
        bool g0 = (c == lb0);
        float e0 = g0 ? (1.0f - p0) : p0;
        __stcs(erow, e0);
        int b0 = lsvF_bin(e0);
        if (b0 >= mb)
            atomicAdd((g0 ? lsvF_hpos : lsvF_hneg) + c * LSV_BINS + b0, 1u);

        float p1 = v[c].y * inv1;
        bool g1 = (c == lb1);
        float e1 = g1 ? (1.0f - p1) : p1;
        __stcs(erow + 1, e1);
        int b1 = lsvF_bin(e1);
        if (b1 >= mb)
            atomicAdd((g1 ? lsvF_hpos : lsvF_hneg) + c * LSV_BINS + b1, 1u);
    }
}

// ---------------------------------------------------------------------------
// Scan: per-class Lovasz loss from split histograms (single pass, one fp64
// div per nonempty bin). j(cnt,cp) = 1 - (P-cp)/(P+cnt-cp), j(0,0) := 0.
// ---------------------------------------------------------------------------
__global__ void __launch_bounds__(1024) lsvF_scan() {
    const int c = blockIdx.x;
    const unsigned int* hn = lsvF_hneg + (size_t)c * LSV_BINS;
    const unsigned int* hp = lsvF_hpos + (size_t)c * LSV_BINS;
    int t = threadIdx.x, lane = t & 31, wid = t >> 5;

    unsigned int xn[LSV_KPB], xp[LSV_KPB];
    unsigned long long tot = 0ull;   // count | positives<<32
#pragma unroll
    for (int k = 0; k < LSV_KPB; k++) {
        int b = LSV_BINS - 1 - (t * LSV_KPB + k);
        xn[k] = hn[b]; xp[k] = hp[b];
        tot += (unsigned long long)(xn[k] + xp[k])
             + ((unsigned long long)xp[k] << 32);
    }

    __shared__ unsigned long long wsum[32];
    unsigned long long v = tot;
#pragma unroll
    for (int off = 1; off < 32; off <<= 1) {
        unsigned long long u = __shfl_up_sync(0xffffffffu, v, off);
        if (lane >= off) v += u;
    }
    if (lane == 31) wsum[wid] = v;
    __syncthreads();
    if (wid == 0) {
        unsigned long long w = wsum[lane];
#pragma unroll
        for (int off = 1; off < 32; off <<= 1) {
            unsigned long long u = __shfl_up_sync(0xffffffffu, w, off);
            if (lane >= off) w += u;
        }
        wsum[lane] = w;
    }
    __syncthreads();
    unsigned long long excl = v - tot;
    if (wid > 0) excl += wsum[wid - 1];
    long long P = (long long)(wsum[31] >> 32);

    long long cnt = (long long)(excl & 0xffffffffull);
    long long cp  = (long long)(excl >> 32);
    double jprev = (cnt == 0) ? 0.0
                 : 1.0 - (double)(P - cp) / (double)(P + cnt - cp);
    double loss = 0.0;
#pragma unroll
    for (int k = 0; k < LSV_KPB; k++) {
        int b = LSV_BINS - 1 - (t * LSV_KPB + k);
        long long nb = (long long)xn[k] + xp[k];
        if (nb > 0) {
            cnt += nb; cp += xp[k];
            double j1 = 1.0 - (double)(P - cp) / (double)(P + cnt - cp);
            loss += (((double)b + 0.5) / (double)LSV_BINS) * (j1 - jprev);
            jprev = j1;
        }
    }

    __shared__ double sl[32];
#pragma unroll
    for (int off = 16; off > 0; off >>= 1)
        loss += __shfl_down_sync(0xffffffffu, loss, off);
    if (lane == 0) sl[wid] = loss;
    __syncthreads();
    if (wid == 0) {
        double l = sl[lane];
#pragma unroll
        for (int off = 16; off > 0; off >>= 1)
            l += __shfl_down_sync(0xffffffffu, l, off);
        if (lane == 0) lsvF_cls_loss[c] = l;
    }
}

// ---------------------------------------------------------------------------
__global__ void lsvF_finalize(float* __restrict__ out) {
    double s = 0.0;
#pragma unroll
    for (int c = 0; c < LSV_CLS; c++) s += lsvF_cls_loss[c];
    out[0] = (float)(s / (double)LSV_CLS);
}

// ---------------------------------------------------------------------------
extern "C" void kernel_launch(void* const* d_in, const int* in_sizes, int n_in,
                              void* d_out, int out_size) {
    const float* logits = (const float*)d_in[0];
    const int*   lblw   = (const int*)d_in[1];
    float* out = (float*)d_out;

    const long long full = (long long)LSV_CLS * LSV_MPIX;
    long long off = (long long)out_size - full;
    if (off < 0) off = 0;
    float* errs_ptr = out + off;

    lsvF_zero<<<(LSV_CLS * LSV_BINS + 255) / 256, 256>>>();
    lsvF_detect<<<(LSV_MPIX / 2 + 255) / 256, 256>>>(lblw);
    lsvF_minpos<<<LSV_MPIX / 1024, 256>>>(logits, lblw);
    lsvF_prep<<<LSV_PNB, 256>>>(logits, lblw, errs_ptr);
    lsvF_scan<<<LSV_CLS, 1024>>>();
    if (off > 0) lsvF_finalize<<<1, 1>>>(out);
}

// round 16
// speedup vs baseline: 2.3055x; 1.2902x over previous
#include <cuda_runtime.h>

// LovaszSoftmaxV1 — histogram/Abel-summation (no sort). R16 = R13 verbatim
// + __launch_bounds__(256, 4) on prep: 64-reg budget keeps v[19] in
// registers (R13 spilled at its self-chosen 32-reg budget). R15's 2px/float2
// layout regressed (store wavefronts doubled) and is reverted.

#define LSV_CLS  19
#define LSV_HW   (384 * 384)           // 147456
#define LSV_MPIX (8 * LSV_HW)          // 1179648
#define LSV_BINS 2048
#define LSV_KPB  2                     // bins per thread in scan

#define LSV_MPB  1024                  // minpos: pixels per block (256 x 4)
#define LSV_MNB  (LSV_MPIX / LSV_MPB)  // 1152
#define LSV_PNB  (LSV_MPIX / 256)      // prep: 4608 blocks, 1 px/thread

__device__ unsigned int lsvG_hneg[LSV_CLS * LSV_BINS];
__device__ unsigned int lsvG_hpos[LSV_CLS * LSV_BINS];
__device__ int          lsvG_minbin[LSV_CLS];
__device__ double       lsvG_cls_loss[LSV_CLS];
__device__ int          lsvG_lbl_is32;

__device__ __forceinline__ int lsvG_bin(float e) {
    int b = (int)(e * (float)LSV_BINS);
    return min(max(b, 0), LSV_BINS - 1);
}

// ---------------------------------------------------------------------------
__global__ void lsvG_zero() {
    int i = blockIdx.x * blockDim.x + threadIdx.x;
    if (i < LSV_CLS * LSV_BINS) { lsvG_hneg[i] = 0u; lsvG_hpos[i] = 0u; }
    if (i < LSV_CLS) lsvG_minbin[i] = 0x7fffffff;
    if (i == 0) lsvG_lbl_is32 = 0;
}

// ---------------------------------------------------------------------------
// Label dtype detector (int32 vs int64): odd int32-words of an int64(<19)
// little-endian buffer are all zero.
// ---------------------------------------------------------------------------
__global__ void __launch_bounds__(256) lsvG_detect(const int* __restrict__ w) {
    int i = blockIdx.x * blockDim.x + threadIdx.x;
    int idx = 2 * i + 1;
    int v = (idx < LSV_MPIX) ? w[idx] : 0;
    for (int off = 16; off > 0; off >>= 1)
        v |= __shfl_down_sync(0xffffffffu, v, off);
    if ((threadIdx.x & 31) == 0 && v != 0) atomicOr(&lsvG_lbl_is32, 1);
}

// ---------------------------------------------------------------------------
// Kernel 1: min positive bin per class — online, low-reg, fully coalesced
// (4 px/thread strided by 256; every access = 1 line/warp). R13 form.
// ---------------------------------------------------------------------------
__global__ void __launch_bounds__(256) lsvG_minpos(
    const float* __restrict__ logits,
    const int* __restrict__ lblw)
{
    __shared__ int smin[LSV_CLS];
    int tid = threadIdx.x;
    if (tid < LSV_CLS) smin[tid] = 0x7fffffff;
    __syncthreads();

    int base_m = blockIdx.x * LSV_MPB + tid;
    int n  = base_m / LSV_HW;          // whole block shares one image
    int hw0 = base_m - n * LSV_HW;
    const float* lg = logits + (size_t)n * (LSV_CLS * LSV_HW) + hw0;
    int is32 = lsvG_lbl_is32;

    int lb[4];
    float s[4]    = {0.f, 0.f, 0.f, 0.f};
    float evlb[4] = {0.f, 0.f, 0.f, 0.f};
#pragma unroll
    for (int i = 0; i < 4; i++) {
        int m = base_m + i * 256;
        lb[i] = is32 ? lblw[m] : lblw[2 * m];
    }
#pragma unroll
    for (int c = 0; c < LSV_CLS; c++) {
        const float* row = lg + (size_t)c * LSV_HW;
#pragma unroll
        for (int i = 0; i < 4; i++) {
            float ev = __expf(__ldcs(row + i * 256));
            s[i] += ev;
            if (c == lb[i]) evlb[i] = ev;
        }
    }
#pragma unroll
    for (int i = 0; i < 4; i++) {
        if ((unsigned)lb[i] < LSV_CLS) {
            float e = 1.0f - evlb[i] / s[i];
            atomicMin(&smin[lb[i]], lsvG_bin(e));
        }
    }
    __syncthreads();
    if (tid < LSV_CLS && smin[tid] != 0x7fffffff)
        atomicMin(&lsvG_minbin[tid], smin[tid]);
}

// ---------------------------------------------------------------------------
// Kernel 2: single-pass prep, 1 pixel/thread, 64-reg budget so v[19] stays
// register-resident (no local-memory spills). 19 front-batched LDGs, 19
// coalesced streaming stores, filtered atomics (Delta-j == 0 below bound).
// ---------------------------------------------------------------------------
__global__ void __launch_bounds__(256, 4) lsvG_prep(
    const float* __restrict__ logits,
    const int* __restrict__ lblw,
    float* __restrict__ errs)
{
    __shared__ int smb[LSV_CLS];
    int tid = threadIdx.x;
    if (tid < LSV_CLS) {
        int mb = lsvG_minbin[tid];
        smb[tid] = (mb == 0x7fffffff) ? 0 : mb;
    }
    __syncthreads();

    int m  = blockIdx.x * 256 + tid;
    int n  = m / LSV_HW;
    int hw = m - n * LSV_HW;
    const float* lg = logits + (size_t)n * (LSV_CLS * LSV_HW) + hw;
    int lb = lsvG_lbl_is32 ? lblw[m] : lblw[2 * m];

    float v[LSV_CLS];
#pragma unroll
    for (int c = 0; c < LSV_CLS; c++)
        v[c] = __ldcs(lg + (size_t)c * LSV_HW);

    float s = 0.f;
#pragma unroll
    for (int c = 0; c < LSV_CLS; c++) {
        v[c] = __expf(v[c]);
        s += v[c];
    }
    float inv = 1.0f / s;

#pragma unroll
    for (int c = 0; c < LSV_CLS; c++) {
        float p = v[c] * inv;
        bool g = (c == lb);
        float e = g ? (1.0f - p) : p;
        __stcs(errs + (size_t)c * LSV_MPIX + m, e);
        int bin = lsvG_bin(e);
        if (bin >= smb[c]) {
            unsigned int* h = g ? lsvG_hpos : lsvG_hneg;
            atomicAdd(&h[c * LSV_BINS + bin], 1u);
        }
    }
}

// ---------------------------------------------------------------------------
// Scan: per-class Lovasz loss from split histograms (single pass, one fp64
// div per nonempty bin). j(cnt,cp) = 1 - (P-cp)/(P+cnt-cp), j(0,0) := 0.
// ---------------------------------------------------------------------------
__global__ void __launch_bounds__(1024) lsvG_scan() {
    const int c = blockIdx.x;
    const unsigned int* hn = lsvG_hneg + (size_t)c * LSV_BINS;
    const unsigned int* hp = lsvG_hpos + (size_t)c * LSV_BINS;
    int t = threadIdx.x, lane = t & 31, wid = t >> 5;

    unsigned int xn[LSV_KPB], xp[LSV_KPB];
    unsigned long long tot = 0ull;   // count | positives<<32
#pragma unroll
    for (int k = 0; k < LSV_KPB; k++) {
        int b = LSV_BINS - 1 - (t * LSV_KPB + k);
        xn[k] = hn[b]; xp[k] = hp[b];
        tot += (unsigned long long)(xn[k] + xp[k])
             + ((unsigned long long)xp[k] << 32);
    }

    __shared__ unsigned long long wsum[32];
    unsigned long long v = tot;
#pragma unroll
    for (int off = 1; off < 32; off <<= 1) {
        unsigned long long u = __shfl_up_sync(0xffffffffu, v, off);
        if (lane >= off) v += u;
    }
    if (lane == 31) wsum[wid] = v;
    __syncthreads();
    if (wid == 0) {
        unsigned long long w = wsum[lane];
#pragma unroll
        for (int off = 1; off < 32; off <<= 1) {
            unsigned long long u = __shfl_up_sync(0xffffffffu, w, off);
            if (lane >= off) w += u;
        }
        wsum[lane] = w;
    }
    __syncthreads();
    unsigned long long excl = v - tot;
    if (wid > 0) excl += wsum[wid - 1];
    long long P = (long long)(wsum[31] >> 32);

    long long cnt = (long long)(excl & 0xffffffffull);
    long long cp  = (long long)(excl >> 32);
    double jprev = (cnt == 0) ? 0.0
                 : 1.0 - (double)(P - cp) / (double)(P + cnt - cp);
    double loss = 0.0;
#pragma unroll
    for (int k = 0; k < LSV_KPB; k++) {
        int b = LSV_BINS - 1 - (t * LSV_KPB + k);
        long long nb = (long long)xn[k] + xp[k];
        if (nb > 0) {
            cnt += nb; cp += xp[k];
            double j1 = 1.0 - (double)(P - cp) / (double)(P + cnt - cp);
            loss += (((double)b + 0.5) / (double)LSV_BINS) * (j1 - jprev);
            jprev = j1;
        }
    }

    __shared__ double sl[32];
#pragma unroll
    for (int off = 16; off > 0; off >>= 1)
        loss += __shfl_down_sync(0xffffffffu, loss, off);
    if (lane == 0) sl[wid] = loss;
    __syncthreads();
    if (wid == 0) {
        double l = sl[lane];
#pragma unroll
        for (int off = 16; off > 0; off >>= 1)
            l += __shfl_down_sync(0xffffffffu, l, off);
        if (lane == 0) lsvG_cls_loss[c] = l;
    }
}

// ---------------------------------------------------------------------------
__global__ void lsvG_finalize(float* __restrict__ out) {
    double s = 0.0;
#pragma unroll
    for (int c = 0; c < LSV_CLS; c++) s += lsvG_cls_loss[c];
    out[0] = (float)(s / (double)LSV_CLS);
}

// ---------------------------------------------------------------------------
extern "C" void kernel_launch(void* const* d_in, const int* in_sizes, int n_in,
                              void* d_out, int out_size) {
    const float* logits = (const float*)d_in[0];
    const int*   lblw   = (const int*)d_in[1];
    float* out = (float*)d_out;

    const long long full = (long long)LSV_CLS * LSV_MPIX;
    long long off = (long long)out_size - full;
    if (off < 0) off = 0;
    float* errs_ptr = out + off;

    lsvG_zero<<<(LSV_CLS * LSV_BINS + 255) / 256, 256>>>();
    lsvG_detect<<<(LSV_MPIX / 2 + 255) / 256, 256>>>(lblw);
    lsvG_minpos<<<LSV_MNB, 256>>>(logits, lblw);
    lsvG_prep<<<LSV_PNB, 256>>>(logits, lblw, errs_ptr);
    lsvG_scan<<<LSV_CLS, 1024>>>();
    if (off > 0) lsvG_finalize<<<1, 1>>>(out);
}